// round 1
// baseline (speedup 1.0000x reference)
#include <cuda_runtime.h>

// WENO-Z 1-D periodic reconstruction, B=16 rows of N=2^20 fp32.
// Memory-bound: 1 read + 1 write per element. Shared-memory halo tile.

#define N_ELEMS   1048576        // N per row (power of two)
#define N_MASK    (N_ELEMS - 1)
#define TPB       256
#define VEC       4
#define TILE      (TPB * VEC)    // 1024 elements per CTA

#define EPS 1e-13f

__global__ void __launch_bounds__(TPB) weno_z_kernel(
    const float* __restrict__ x, float* __restrict__ out)
{
    __shared__ float s[TILE + 8];   // [0..3]=left pad (data at 1..3), [4..4+TILE)=tile, [4+TILE]=right halo

    const int b     = blockIdx.y;
    const int start = blockIdx.x * TILE;
    const float* xb = x + (size_t)b * N_ELEMS;
    const int t = threadIdx.x;

    // main tile load: fully coalesced float4
    float4 v = *reinterpret_cast<const float4*>(xb + start + t * VEC);
    *reinterpret_cast<float4*>(&s[4 + t * VEC]) = v;

    // halos (periodic wrap)
    if (t < 3) {
        s[1 + t] = xb[(start - 3 + t) & N_MASK];
    } else if (t == 3) {
        s[4 + TILE] = xb[(start + TILE) & N_MASK];
    }
    __syncthreads();

    float4 o;
    float* op = &o.x;

    #pragma unroll
    for (int j = 0; j < VEC; j++) {
        const int i = 4 + t * VEC + j;     // smem index of x[n]
        const float x0 = s[i - 3];
        const float x1 = s[i - 2];
        const float x2 = s[i - 1];
        const float x3 = s[i];
        const float x4 = s[i + 1];

        // stencil derivatives (S rows)
        const float a0 = x0 - 2.0f * x1 + x2;
        const float a1 = x0 - 4.0f * x1 + 3.0f * x2;
        const float a2 = x1 - 2.0f * x2 + x3;
        const float a3 = x1 - x3;
        const float a4 = x2 - 2.0f * x3 + x4;
        const float a5 = 3.0f * x2 - 4.0f * x3 + x4;

        const float c1312 = 13.0f / 12.0f;
        const float IS0 = c1312 * a0 * a0 + 0.25f * a1 * a1;
        const float IS1 = c1312 * a2 * a2 + 0.25f * a3 * a3;
        const float IS2 = c1312 * a4 * a4 + 0.25f * a5 * a5;

        const float T5 = fabsf(IS2 - IS0);

        const float w0 = 0.1f * (1.0f + __fdividef(T5, IS0 + EPS));
        const float w1 = 0.6f * (1.0f + __fdividef(T5, IS1 + EPS));
        const float w2 = 0.3f * (1.0f + __fdividef(T5, IS2 + EPS));

        const float inv6 = 1.0f / 6.0f;
        const float P0 = (2.0f * x0 - 7.0f * x1 + 11.0f * x2) * inv6;
        const float P1 = (-x1 + 5.0f * x2 + 2.0f * x3) * inv6;
        const float P2 = (2.0f * x2 + 5.0f * x3 - x4) * inv6;

        op[j] = __fdividef(w0 * P0 + w1 * P1 + w2 * P2, w0 + w1 + w2);
    }

    *reinterpret_cast<float4*>(out + (size_t)b * N_ELEMS + start + t * VEC) = o;
}

extern "C" void kernel_launch(void* const* d_in, const int* in_sizes, int n_in,
                              void* d_out, int out_size)
{
    const float* x = (const float*)d_in[0];
    float* out = (float*)d_out;
    const int total = in_sizes[0];
    const int batches = total / N_ELEMS;   // 16

    dim3 grid(N_ELEMS / TILE, batches);    // (1024, 16)
    weno_z_kernel<<<grid, TPB>>>(x, out);
}

// round 2
// speedup vs baseline: 1.4071x; 1.4071x over previous
#include <cuda_runtime.h>

// WENO-Z 1-D periodic, B=16 x N=2^20 fp32.
// Issue-bound -> packed f32x2 math, division-free weights, vector LDS.

#define N_ELEMS   1048576
#define N_MASK    (N_ELEMS - 1)
#define TPB       256
#define VEC       4
#define TILE      (TPB * VEC)    // 1024

#define EPS 1e-13f

typedef unsigned long long u64;

__device__ __forceinline__ u64 pk(float lo, float hi) {
    u64 r; asm("mov.b64 %0, {%1, %2};" : "=l"(r) : "f"(lo), "f"(hi)); return r;
}
__device__ __forceinline__ void upk(float& lo, float& hi, u64 v) {
    asm("mov.b64 {%0, %1}, %2;" : "=f"(lo), "=f"(hi) : "l"(v));
}
__device__ __forceinline__ u64 f2mul(u64 a, u64 b) {
    u64 d; asm("mul.rn.f32x2 %0, %1, %2;" : "=l"(d) : "l"(a), "l"(b)); return d;
}
__device__ __forceinline__ u64 f2add(u64 a, u64 b) {
    u64 d; asm("add.rn.f32x2 %0, %1, %2;" : "=l"(d) : "l"(a), "l"(b)); return d;
}
__device__ __forceinline__ u64 f2fma(u64 a, u64 b, u64 c) {
    u64 d; asm("fma.rn.f32x2 %0, %1, %2, %3;" : "=l"(d) : "l"(a), "l"(b), "l"(c)); return d;
}
__device__ __forceinline__ u64 f2abs(u64 a) { return a & 0x7FFFFFFF7FFFFFFFULL; }

// One WENO-Z evaluation for a pair of adjacent outputs, fully packed.
// X0..X4 are the 5 stencil values (each packed: lane0 = output j, lane1 = output j+1).
// Returns packed (num, den) via references.
__device__ __forceinline__ void weno_pair(
    u64 X0, u64 X1, u64 X2, u64 X3, u64 X4, u64& num, u64& den)
{
    const u64 Cm2   = pk(-2.0f, -2.0f);
    const u64 Cm4   = pk(-4.0f, -4.0f);
    const u64 C3    = pk(3.0f, 3.0f);
    const u64 Cm1   = pk(-1.0f, -1.0f);
    const u64 C1312 = pk(13.0f/12.0f, 13.0f/12.0f);
    const u64 Cq    = pk(0.25f, 0.25f);
    const u64 Cmq   = pk(-0.25f, -0.25f);
    const u64 C112  = pk(1.0f/12.0f, 1.0f/12.0f);
    const u64 Cm512 = pk(-5.0f/12.0f, -5.0f/12.0f);
    const u64 Ceps  = pk(EPS, EPS);
    const u64 D0    = pk(0.1f, 0.1f);
    const u64 D1    = pk(0.6f, 0.6f);
    const u64 D2    = pk(0.3f, 0.3f);

    // stencil second/first differences
    u64 a0 = f2fma(X1, Cm2, f2add(X0, X2));          // x0 - 2x1 + x2
    u64 a1 = f2fma(X2, C3,  f2fma(X1, Cm4, X0));     // x0 - 4x1 + 3x2
    u64 a2 = f2fma(X2, Cm2, f2add(X1, X3));          // x1 - 2x2 + x3
    u64 a3 = f2fma(X1, Cm1, X3);                     // x3 - x1  (= -(x1-x3); squared below, sign folded into P1)
    u64 a4 = f2fma(X3, Cm2, f2add(X2, X4));          // x2 - 2x3 + x4
    u64 a5 = f2fma(X3, Cm4, f2fma(X2, C3, X4));      // 3x2 - 4x3 + x4

    u64 IS0 = f2fma(f2mul(a0, a0), C1312, f2mul(f2mul(a1, a1), Cq));
    u64 IS1 = f2fma(f2mul(a2, a2), C1312, f2mul(f2mul(a3, a3), Cq));
    u64 IS2 = f2fma(f2mul(a4, a4), C1312, f2mul(f2mul(a5, a5), Cq));

    u64 T5 = f2abs(f2fma(IS0, Cm1, IS2));            // |IS2 - IS0|

    u64 e0 = f2add(IS0, Ceps);
    u64 e1 = f2add(IS1, Ceps);
    u64 e2 = f2add(IS2, Ceps);

    // g_i = d_i * (IS_i + eps + T5);  w~_i = g_i * prod_{j!=i}(IS_j + eps)
    u64 g0 = f2mul(D0, f2add(e0, T5));
    u64 g1 = f2mul(D1, f2add(e1, T5));
    u64 g2 = f2mul(D2, f2add(e2, T5));
    u64 w0 = f2mul(g0, f2mul(e1, e2));
    u64 w1 = f2mul(g1, f2mul(e0, e2));
    u64 w2 = f2mul(g2, f2mul(e0, e1));

    // Lagrange candidates via stencil-derivative identities:
    // P0 = a0/12 + a1/4 + x2 ; P1 = a2/12 - (x1-x3)/4 + x2 = a2/12 + a3/4 + x2 (a3 = x3-x1... sign check below)
    // P2 = -5/12 a4 + 1/4 a5 + x3
    // Reference P1 = (-x1 + 5x2 + 2x3)/6 = a2/12 - (1/4)(x1 - x3) + x2 = a2/12 + (1/4)(x3 - x1) + x2
    u64 P0 = f2fma(a0, C112, f2fma(a1, Cq, X2));
    u64 P1 = f2fma(a2, C112, f2fma(a3, Cq, X2));     // a3 = x3 - x1, coefficient +1/4
    u64 P2 = f2fma(a4, Cm512, f2fma(a5, Cq, X3));

    num = f2fma(w2, P2, f2fma(w1, P1, f2mul(w0, P0)));
    den = f2add(w0, f2add(w1, w2));
    (void)Cmq;
}

__global__ void __launch_bounds__(TPB) weno_z_kernel(
    const float* __restrict__ x, float* __restrict__ out)
{
    __shared__ __align__(16) float s[TILE + 12];
    // layout: s[4 + k] = x[start + k] for k in [0, TILE); s[1..3] = left halo; s[TILE+4] = right halo.

    const int b     = blockIdx.y;
    const int start = blockIdx.x * TILE;
    const float* xb = x + (size_t)b * N_ELEMS;
    const int t     = threadIdx.x;

    float4 v = *reinterpret_cast<const float4*>(xb + start + t * VEC);
    *reinterpret_cast<float4*>(&s[4 + t * VEC]) = v;

    if (t < 3) {
        s[1 + t] = xb[(start - 3 + t) & N_MASK];
    } else if (t == 3) {
        s[TILE + 4] = xb[(start + TILE) & N_MASK];
    }
    __syncthreads();

    // p[k] = x[n0 - 4 + k], k = 0..8 ; n0 = start + t*4
    const float4 lo4 = *reinterpret_cast<const float4*>(&s[t * VEC]);       // p0..p3
    const float4 hi4 = *reinterpret_cast<const float4*>(&s[t * VEC + 4]);   // p4..p7
    const float  p8  = s[t * VEC + 8];

    const float p1 = lo4.y, p2 = lo4.z, p3 = lo4.w;
    const float p4 = hi4.x, p5 = hi4.y, p6 = hi4.z, p7 = hi4.w;

    const u64 P12 = pk(p1, p2);
    const u64 P23 = pk(p2, p3);
    const u64 P34 = pk(p3, p4);
    const u64 P45 = pk(p4, p5);
    const u64 P56 = pk(p5, p6);
    const u64 P67 = pk(p6, p7);
    const u64 P78 = pk(p7, p8);

    u64 numA, denA, numB, denB;
    // pair A: outputs j=0,1 -> stencils p[1..5], p[2..6]
    weno_pair(P12, P23, P34, P45, P56, numA, denA);
    // pair B: outputs j=2,3 -> stencils p[3..7], p[4..8]
    weno_pair(P34, P45, P56, P67, P78, numB, denB);

    float n0f, n1f, n2f, n3f, d0f, d1f, d2f, d3f;
    upk(n0f, n1f, numA); upk(d0f, d1f, denA);
    upk(n2f, n3f, numB); upk(d2f, d3f, denB);

    float4 o;
    o.x = __fdividef(n0f, d0f);
    o.y = __fdividef(n1f, d1f);
    o.z = __fdividef(n2f, d2f);
    o.w = __fdividef(n3f, d3f);

    *reinterpret_cast<float4*>(out + (size_t)b * N_ELEMS + start + t * VEC) = o;
}

extern "C" void kernel_launch(void* const* d_in, const int* in_sizes, int n_in,
                              void* d_out, int out_size)
{
    const float* x = (const float*)d_in[0];
    float* out = (float*)d_out;
    const int total = in_sizes[0];
    const int batches = total / N_ELEMS;

    dim3 grid(N_ELEMS / TILE, batches);
    weno_z_kernel<<<grid, TPB>>>(x, out);
}

// round 3
// speedup vs baseline: 1.5918x; 1.1313x over previous
#include <cuda_runtime.h>

// WENO-Z 1-D periodic, B=16 x N=2^20 fp32.
// fma-pipe-bound -> shared d1/d2 stencil differences + packed f32x2 + VEC=8.

#define N_ELEMS   1048576
#define N_MASK    (N_ELEMS - 1)
#define TPB       128
#define VEC       8
#define TILE      (TPB * VEC)    // 1024

#define EPS 1e-13f

typedef unsigned long long u64;

__device__ __forceinline__ u64 pk(float lo, float hi) {
    u64 r; asm("mov.b64 %0, {%1, %2};" : "=l"(r) : "f"(lo), "f"(hi)); return r;
}
__device__ __forceinline__ void upk(float& lo, float& hi, u64 v) {
    asm("mov.b64 {%0, %1}, %2;" : "=f"(lo), "=f"(hi) : "l"(v));
}
__device__ __forceinline__ u64 f2mul(u64 a, u64 b) {
    u64 d; asm("mul.rn.f32x2 %0, %1, %2;" : "=l"(d) : "l"(a), "l"(b)); return d;
}
__device__ __forceinline__ u64 f2add(u64 a, u64 b) {
    u64 d; asm("add.rn.f32x2 %0, %1, %2;" : "=l"(d) : "l"(a), "l"(b)); return d;
}
__device__ __forceinline__ u64 f2fma(u64 a, u64 b, u64 c) {
    u64 d; asm("fma.rn.f32x2 %0, %1, %2, %3;" : "=l"(d) : "l"(a), "l"(b), "l"(c)); return d;
}
__device__ __forceinline__ u64 f2abs(u64 a) { return a & 0x7FFFFFFF7FFFFFFFULL; }

__global__ void __launch_bounds__(TPB) weno_z_kernel(
    const float* __restrict__ x, float* __restrict__ out)
{
    __shared__ __align__(16) float s[TILE + 16];
    // s[4 + k] = x[start + k] for k in [-4, TILE+8)

    const int b     = blockIdx.y;
    const int start = blockIdx.x * TILE;
    const float* xb = x + (size_t)b * N_ELEMS;
    const int t     = threadIdx.x;

    float4 va = *reinterpret_cast<const float4*>(xb + start + t * VEC);
    float4 vb = *reinterpret_cast<const float4*>(xb + start + t * VEC + 4);
    *reinterpret_cast<float4*>(&s[4 + t * VEC])     = va;
    *reinterpret_cast<float4*>(&s[4 + t * VEC + 4]) = vb;

    if (t < 4) {
        s[t] = xb[(start - 4 + t) & N_MASK];              // left halo: x[start-4..start-1]
    } else if (t < 12) {
        s[TILE + t] = xb[(start + TILE + t - 4) & N_MASK]; // right halo: x[start+TILE..+7]
    }
    __syncthreads();

    // p[k] = x[n0 - 4 + k], k = 0..12 ; outputs at p-index m = 4..11
    float p[13];
    float4 f0 = *reinterpret_cast<const float4*>(&s[t * VEC]);
    float4 f1 = *reinterpret_cast<const float4*>(&s[t * VEC + 4]);
    float4 f2v = *reinterpret_cast<const float4*>(&s[t * VEC + 8]);
    p[0]=f0.x; p[1]=f0.y; p[2]=f0.z; p[3]=f0.w;
    p[4]=f1.x; p[5]=f1.y; p[6]=f1.z; p[7]=f1.w;
    p[8]=f2v.x; p[9]=f2v.y; p[10]=f2v.z; p[11]=f2v.w;
    p[12] = s[t * VEC + 12];

    const u64 Cm1   = pk(-1.0f, -1.0f);
    const u64 C05   = pk(0.5f, 0.5f);
    const u64 Cm05  = pk(-0.5f, -0.5f);
    const u64 C1312 = pk(13.0f/12.0f, 13.0f/12.0f);
    const u64 C112  = pk(1.0f/12.0f, 1.0f/12.0f);
    const u64 Cm512 = pk(-5.0f/12.0f, -5.0f/12.0f);
    const u64 Ceps  = pk(EPS, EPS);
    const u64 Cd0   = pk(0.1f, 0.1f);
    const u64 Cd1   = pk(0.6f, 0.6f);
    const u64 Cd2   = pk(0.3f, 0.3f);

    // Pp[i] = (p[i+1], p[i+2]), i = 0..10
    u64 Pp[11];
    #pragma unroll
    for (int i = 0; i < 11; i++) Pp[i] = pk(p[i + 1], p[i + 2]);

    // D1[i] = (d1[i+2], d1[i+3]) where d1[k] = p[k]-p[k-1] ; i = 0..9
    u64 D1[10];
    #pragma unroll
    for (int i = 0; i < 10; i++) D1[i] = f2fma(Pp[i], Cm1, Pp[i + 1]);

    // D2[i] = (d2[i+2], d2[i+3]) where d2[k] = d1[k+1]-d1[k] ; i = 0..8
    // SQ[i] = 13/12 * d2^2 + EPS  (shared across up to 3 smoothness indicators)
    u64 D2[9], SQ[9];
    #pragma unroll
    for (int i = 0; i < 9; i++) {
        D2[i] = f2fma(D1[i], Cm1, D1[i + 1]);
        SQ[i] = f2fma(f2mul(D2[i], D2[i]), C1312, Ceps);
    }

    float o[VEC];

    #pragma unroll
    for (int q = 0; q < 4; q++) {
        // outputs m = 4+2q (lane0) and m+1 (lane1)
        const u64 A0  = D2[2*q];       // (d2[m-2], d2[m-1])
        const u64 A2  = D2[2*q + 1];   // (d2[m-1], d2[m])
        const u64 A4  = D2[2*q + 2];   // (d2[m],   d2[m+1])
        const u64 D1a = D1[2*q + 1];   // (d1[m-1], d1[m])
        const u64 D1b = D1[2*q + 2];   // (d1[m],   d1[m+1])
        const u64 X2  = Pp[2*q + 2];   // (p[m-1],  p[m])
        const u64 X3  = Pp[2*q + 3];   // (p[m],    p[m+1])

        // half-amplitude odd coefficients: b1 = a1/2, b3 = a3/2, b5n = -a5/2
        const u64 B1  = f2fma(A0, C05, D1a);
        const u64 B3  = f2mul(f2add(D1a, D1b), C05);
        const u64 B5n = f2fma(A4, Cm05, D1b);

        const u64 IS0 = f2fma(B1,  B1,  SQ[2*q]);
        const u64 IS1 = f2fma(B3,  B3,  SQ[2*q + 1]);
        const u64 IS2 = f2fma(B5n, B5n, SQ[2*q + 2]);

        const u64 T5 = f2abs(f2fma(IS0, Cm1, IS2));    // |IS2 - IS0|

        const u64 t0 = f2add(IS0, T5);
        const u64 t1 = f2add(IS1, T5);
        const u64 t2 = f2add(IS2, T5);
        const u64 g0 = f2mul(Cd0, t0);
        const u64 g1 = f2mul(Cd1, t1);
        const u64 g2 = f2mul(Cd2, t2);
        const u64 e01 = f2mul(IS0, IS1);
        const u64 e02 = f2mul(IS0, IS2);
        const u64 e12 = f2mul(IS1, IS2);
        const u64 w0 = f2mul(g0, e12);
        const u64 w1 = f2mul(g1, e02);
        const u64 w2 = f2mul(g2, e01);

        // P0 = x2 + a0/12 + b1/2 ; P1 = x2 + a2/12 + b3/2 ; P2 = x3 - 5/12 a4 - b5n/2
        const u64 P0 = f2fma(A0, C112,  f2fma(B1,  C05,  X2));
        const u64 P1 = f2fma(A2, C112,  f2fma(B3,  C05,  X2));
        const u64 P2 = f2fma(A4, Cm512, f2fma(B5n, Cm05, X3));

        const u64 num = f2fma(w2, P2, f2fma(w1, P1, f2mul(w0, P0)));
        const u64 den = f2add(f2add(w0, w1), w2);

        float n0, n1, d0, d1;
        upk(n0, n1, num); upk(d0, d1, den);
        o[2*q]     = __fdividef(n0, d0);
        o[2*q + 1] = __fdividef(n1, d1);
    }

    float* ob = out + (size_t)b * N_ELEMS + start + t * VEC;
    *reinterpret_cast<float4*>(ob)     = make_float4(o[0], o[1], o[2], o[3]);
    *reinterpret_cast<float4*>(ob + 4) = make_float4(o[4], o[5], o[6], o[7]);
}

extern "C" void kernel_launch(void* const* d_in, const int* in_sizes, int n_in,
                              void* d_out, int out_size)
{
    const float* x = (const float*)d_in[0];
    float* out = (float*)d_out;
    const int total = in_sizes[0];
    const int batches = total / N_ELEMS;

    dim3 grid(N_ELEMS / TILE, batches);
    weno_z_kernel<<<grid, TPB>>>(x, out);
}